// round 5
// baseline (speedup 1.0000x reference)
#include <cuda_runtime.h>
#include <cuda_bf16.h>
#include <math.h>

// Problem constants
#define VV   32000
#define EE   500
#define HH   500
#define DD1  800
#define DD2  100
#define CC   2
#define BB   64
#define TT   400
#define G4H  2000            // 4*H
#define MM   (BB*TT)         // 25600 rows of the big GEMMs
#define NREC_BLOCKS 125      // 125 * 4 units = 500
#define HPAIRS 256           // padded unit-pairs (250 real) for staging
#define HFLOATS (HPAIRS*128) // 32768 floats = 128KB per h buffer

// ---------------- scratch (device globals; no allocation allowed) ----------------
__device__ float g_xz [(size_t)MM * G4H];     // 204.8 MB, reused for layer1 and layer2
__device__ float g_hs1[(size_t)MM * HH];      // 51.2 MB
__device__ float g_hb0[HFLOATS];
__device__ float g_hb1[HFLOATS];
__device__ float g_d1 [BB * DD1];
__device__ float g_d2 [BB * DD2];
__device__ unsigned g_cnt2   = 0;
__device__ unsigned g_sense2 = 0;

// ---------------- packed f32x2 helpers ----------------
__device__ __forceinline__ unsigned long long pk2(float lo, float hi){
    unsigned long long r;
    asm("mov.b64 %0, {%1, %2};" : "=l"(r) : "f"(lo), "f"(hi));
    return r;
}
__device__ __forceinline__ unsigned long long dup2(float v){
    unsigned long long r;
    asm("mov.b64 %0, {%1, %1};" : "=l"(r) : "f"(v));
    return r;
}
__device__ __forceinline__ void fma2(unsigned long long &d,
                                     unsigned long long a,
                                     unsigned long long b){
    asm("fma.rn.f32x2 %0, %1, %2, %3;" : "=l"(d) : "l"(a), "l"(b), "l"(d));
}
__device__ __forceinline__ void unpk2(unsigned long long v, float &lo, float &hi){
    asm("mov.b64 {%0, %1}, %2;" : "=f"(lo), "=f"(hi) : "l"(v));
}

// ---------------- cp.async helpers ----------------
__device__ __forceinline__ void cp_async16(unsigned saddr, const void* gptr){
    asm volatile("cp.async.cg.shared.global [%0], [%1], 16;"
                 :: "r"(saddr), "l"(gptr) : "memory");
}
#define CP_COMMIT()  asm volatile("cp.async.commit_group;" ::: "memory")
#define CP_WAIT(n)   asm volatile("cp.async.wait_group %0;" :: "n"(n) : "memory")

// =====================================================================
// SGEMM: C[M=25600, N=2000] = A[M,500] @ Bw[500,2000] + bias
// GATHER=1: A row m -> embed[X[b*T+t]] with m = t*64+b
// 128x128 block tile, BK=8, 256 threads, 8x8 per-thread tile, f32x2 math
// =====================================================================
template<int GATHER>
__global__ __launch_bounds__(256)
void sgemm_xz(const int* __restrict__ X, const float* __restrict__ A,
              const float* __restrict__ Bw, const float* __restrict__ bias,
              float* __restrict__ Cmat)
{
    __shared__ float As[8][128];
    __shared__ float Bs[8][128];

    const int tid = threadIdx.x;
    const int tx  = tid & 15;        // 0..15 -> 8 cols each
    const int ty  = tid >> 4;        // 0..15 -> 8 rows each
    const int m0  = blockIdx.y * 128;
    const int n0  = blockIdx.x * 128;

    const int ar  = tid >> 1;
    const int akq = (tid & 1) * 4;
    const float* arow_ptr;
    {
        int m = m0 + ar;
        if (GATHER){
            int t = m >> 6, b = m & 63;
            int tok = X[b * TT + t];
            arow_ptr = A + (size_t)tok * EE;
        } else {
            arow_ptr = A + (size_t)m * HH;
        }
    }
    const int bk = tid >> 5;
    const int bn = (tid & 31) * 4;

    unsigned long long acc[8][4];
    #pragma unroll
    for (int i = 0; i < 8; i++)
        #pragma unroll
        for (int j = 0; j < 4; j++) acc[i][j] = 0ULL;

    const float4 f40 = make_float4(0.f, 0.f, 0.f, 0.f);
    float4 aReg, bReg;
    {
        int k  = akq;
        aReg = (k < 500) ? *(const float4*)(arow_ptr + k) : f40;
        int kb = bk, n = n0 + bn;
        bReg = (kb < 500 && n < G4H) ? *(const float4*)(Bw + (size_t)kb * G4H + n) : f40;
    }

    const int KT = 63;   // ceil(500/8)
    for (int kt = 0; kt < KT; kt++){
        __syncthreads();
        As[akq+0][ar] = aReg.x; As[akq+1][ar] = aReg.y;
        As[akq+2][ar] = aReg.z; As[akq+3][ar] = aReg.w;
        *(float4*)(&Bs[bk][bn]) = bReg;
        __syncthreads();

        if (kt + 1 < KT){
            int k = (kt+1)*8 + akq;
            aReg = (k < 500) ? *(const float4*)(arow_ptr + k) : f40;
            int kb = (kt+1)*8 + bk, n = n0 + bn;
            bReg = (kb < 500 && n < G4H) ? *(const float4*)(Bw + (size_t)kb * G4H + n) : f40;
        }

        #pragma unroll
        for (int kk = 0; kk < 8; kk++){
            float4 a0 = *(const float4*)(&As[kk][ty*8]);
            float4 a1 = *(const float4*)(&As[kk][ty*8 + 4]);
            const unsigned long long* bp2 = (const unsigned long long*)(&Bs[kk][tx*8]);
            unsigned long long b0 = bp2[0], b1 = bp2[1], b2 = bp2[2], b3 = bp2[3];
            float av[8] = {a0.x,a0.y,a0.z,a0.w,a1.x,a1.y,a1.z,a1.w};
            #pragma unroll
            for (int i = 0; i < 8; i++){
                unsigned long long ad = dup2(av[i]);
                fma2(acc[i][0], ad, b0);
                fma2(acc[i][1], ad, b1);
                fma2(acc[i][2], ad, b2);
                fma2(acc[i][3], ad, b3);
            }
        }
    }

    const int nc = n0 + tx * 8;
    if (nc < G4H){
        float4 bb0 = *(const float4*)(bias + nc);
        float4 bb1 = *(const float4*)(bias + nc + 4);
        #pragma unroll
        for (int i = 0; i < 8; i++){
            int m = m0 + ty*8 + i;
            float o[8];
            unpk2(acc[i][0], o[0], o[1]);
            unpk2(acc[i][1], o[2], o[3]);
            unpk2(acc[i][2], o[4], o[5]);
            unpk2(acc[i][3], o[6], o[7]);
            float4 r0 = make_float4(o[0]+bb0.x, o[1]+bb0.y, o[2]+bb0.z, o[3]+bb0.w);
            float4 r1 = make_float4(o[4]+bb1.x, o[5]+bb1.y, o[6]+bb1.z, o[7]+bb1.w);
            float* cp = Cmat + (size_t)m * G4H + nc;
            *(float4*)(cp)     = r0;
            *(float4*)(cp + 4) = r1;
        }
    }
}

// =====================================================================
// Lightweight grid barrier (cooperative-groups pattern):
// bar.sync orders all CTA threads' prior (weak) stores before thread 0's
// acq_rel arrive; last arriver release-stores the sense; pollers acquire-load.
// No per-thread membar.gl, no nanosleep.
// =====================================================================
__device__ __forceinline__ void grid_barrier(int nb, unsigned* s_sense)
{
    __syncthreads();
    if (threadIdx.x == 0){
        unsigned target = *s_sense + 1u;
        unsigned old;
        asm volatile("atom.acq_rel.gpu.global.add.u32 %0, [%1], %2;"
                     : "=r"(old) : "l"(&g_cnt2), "r"(1u) : "memory");
        if (old == (unsigned)(nb - 1)){
            asm volatile("st.relaxed.gpu.global.u32 [%0], %1;"
                         :: "l"(&g_cnt2), "r"(0u) : "memory");
            asm volatile("st.release.gpu.global.u32 [%0], %1;"
                         :: "l"(&g_sense2), "r"(target) : "memory");
        } else {
            unsigned v;
            do {
                asm volatile("ld.acquire.gpu.global.u32 %0, [%1];"
                             : "=r"(v) : "l"(&g_sense2) : "memory");
            } while (v != target);
        }
        *s_sense = target;
    }
    __syncthreads();
}

// =====================================================================
// Persistent LSTM recurrence.
// 125 blocks x 256 threads, 1 block/SM (163KB smem), thread = (b, unit u).
// h global layout: pair-packed h[(k>>1)*128 + b*2 + (k&1)] so the inner loop
// reads h two-at-a-time with LDS.64, weights with LDS.128.
// h_prev staged to SMEM via cp.async.cg in 2 chunks, overlapped with compute.
// =====================================================================
__global__ void lstm_rec(const float* __restrict__ xz, const float* __restrict__ Wh,
                         float* __restrict__ hs_out, int store_hs,
                         float* __restrict__ hb0, float* __restrict__ hb1, int nb)
{
    extern __shared__ float smem[];
    float* hsm = smem;                 // 32768 floats (128 KB)
    float* wsm = smem + HFLOATS;       // 8000 floats (32 KB)
    __shared__ unsigned s_sense;

    const int tid = threadIdx.x;
    const int b   = tid & 63;
    const int u   = tid >> 6;          // 0..3
    const int u0  = blockIdx.x * 4;
    const int uu  = u0 + u;            // this thread's hidden unit

    if (tid == 0){
        unsigned v;
        asm volatile("ld.relaxed.gpu.global.u32 %0, [%1];" : "=r"(v) : "l"(&g_sense2) : "memory");
        s_sense = v;
    }

    // cache weight slice: wsm[k*16 + uw*4 + g] = Wh[k*2000 + g*500 + u0+uw]
    for (int idx = tid; idx < 500 * 16; idx += 256){
        int k = idx >> 4, r = idx & 15;
        int uw = r >> 2, g = r & 3;
        wsm[idx] = Wh[(size_t)k * G4H + g * HH + u0 + uw];
    }

    // zero both h buffers (incl. pad pairs, stay zero forever)
    {
        int gt = blockIdx.x * 256 + tid;
        float4 z4 = make_float4(0.f, 0.f, 0.f, 0.f);
        for (int i = gt; i < HFLOATS / 4; i += nb * 256){
            ((float4*)hb0)[i] = z4;
            ((float4*)hb1)[i] = z4;
        }
    }
    grid_barrier(nb, &s_sense);   // weights loaded + buffers zeroed everywhere

    const unsigned hsm_s = (unsigned)__cvta_generic_to_shared(hsm);
    float cst = 0.f;
    const int hdst = (uu >> 1) * 128 + b * 2 + (uu & 1);

    for (int t = 0; t < TT; t++){
        const float* hprev = (t & 1) ? hb1 : hb0;
        float*       hnext = (t & 1) ? hb0 : hb1;

        // stage h_prev in two 64KB chunks, L1-bypass, async
        #pragma unroll
        for (int cc = 0; cc < 16; cc++){
            int idx = tid + cc * 256;                      // float4 index
            cp_async16(hsm_s + idx * 16, (const float4*)hprev + idx);
        }
        CP_COMMIT();
        #pragma unroll
        for (int cc = 16; cc < 32; cc++){
            int idx = tid + cc * 256;
            cp_async16(hsm_s + idx * 16, (const float4*)hprev + idx);
        }
        CP_COMMIT();

        // xz loads overlap with staging
        size_t mrow = (size_t)(t * BB + b) * G4H + uu;
        float xi = __ldcs(xz + mrow);
        float xj = __ldcs(xz + mrow + 500);
        float xf = __ldcs(xz + mrow + 1000);
        float xo = __ldcs(xz + mrow + 1500);

        unsigned long long aij = pk2(xi, xj);
        unsigned long long afo = pk2(xf, xo);

        CP_WAIT(1);            // chunk 0 (pairs 0..127) resident
        __syncthreads();

        #pragma unroll 4
        for (int p = 0; p < 128; p++){
            float2 h2 = *(const float2*)(hsm + p * 128 + b * 2);
            ulonglong2 wa = *(const ulonglong2*)(wsm + ((2*p    ) * 4 + u) * 4);
            ulonglong2 wb = *(const ulonglong2*)(wsm + ((2*p + 1) * 4 + u) * 4);
            unsigned long long h0 = dup2(h2.x), h1 = dup2(h2.y);
            fma2(aij, h0, wa.x); fma2(afo, h0, wa.y);
            fma2(aij, h1, wb.x); fma2(afo, h1, wb.y);
        }

        CP_WAIT(0);            // chunk 1 (pairs 128..255) resident
        __syncthreads();

        #pragma unroll 4
        for (int p = 128; p < 250; p++){
            float2 h2 = *(const float2*)(hsm + p * 128 + b * 2);
            ulonglong2 wa = *(const ulonglong2*)(wsm + ((2*p    ) * 4 + u) * 4);
            ulonglong2 wb = *(const ulonglong2*)(wsm + ((2*p + 1) * 4 + u) * 4);
            unsigned long long h0 = dup2(h2.x), h1 = dup2(h2.y);
            fma2(aij, h0, wa.x); fma2(afo, h0, wa.y);
            fma2(aij, h1, wb.x); fma2(afo, h1, wb.y);
        }

        float zi, zj, zf, zo;
        unpk2(aij, zi, zj);
        unpk2(afo, zf, zo);

        float ig = 1.f / (1.f + expf(-zi));
        float fg = 1.f / (1.f + expf(-(zf + 1.f)));
        float og = 1.f / (1.f + expf(-zo));
        float jt = tanhf(zj);
        cst = fg * cst + ig * jt;
        float hv = og * tanhf(cst);

        __stcg(hnext + hdst, hv);
        if (store_hs)
            hs_out[(size_t)(t * BB + b) * HH + uu] = hv;

        grid_barrier(nb, &s_sense);
    }
}

// =====================================================================
// Small dense layers. out[b*N + j] = act(sum_k in(b,k)*W[k*N+j] + bias[j])
// transposed_in: in uses the pair-packed h layout; else in[b*K + k]
// =====================================================================
__global__ void dense_kernel(const float* __restrict__ in, const float* __restrict__ W,
                             const float* __restrict__ bias, float* __restrict__ out,
                             int Kdim, int Ndim, int transposed_in, int do_relu)
{
    int g = blockIdx.x * blockDim.x + threadIdx.x;
    if (g >= BB * Ndim) return;
    int bv = g / Ndim;
    int j  = g - bv * Ndim;
    float acc = bias[j];
    if (transposed_in){
        for (int k = 0; k < Kdim; k++)
            acc += in[(k >> 1) * 128 + bv * 2 + (k & 1)] * W[k * Ndim + j];
    } else {
        for (int k = 0; k < Kdim; k++)
            acc += in[bv * Kdim + k] * W[k * Ndim + j];
    }
    out[g] = do_relu ? fmaxf(acc, 0.f) : acc;
}

// =====================================================================
// Launch
// =====================================================================
#define REC_SMEM ((HFLOATS + 500*16) * (int)sizeof(float))   // 163072 B

extern "C" void kernel_launch(void* const* d_in, const int* in_sizes, int n_in,
                              void* d_out, int out_size)
{
    const int*   X     = (const int*)  d_in[0];
    const float* embed = (const float*)d_in[1];
    const float* k1    = (const float*)d_in[2];
    const float* b1    = (const float*)d_in[3];
    const float* k2    = (const float*)d_in[4];
    const float* b2    = (const float*)d_in[5];
    const float* w1    = (const float*)d_in[6];
    const float* bw1   = (const float*)d_in[7];
    const float* w2    = (const float*)d_in[8];
    const float* bw2   = (const float*)d_in[9];
    const float* wp    = (const float*)d_in[10];
    const float* bp    = (const float*)d_in[11];
    float* out = (float*)d_out;

    float *xz, *hs1, *hb0, *hb1, *d1, *d2;
    cudaGetSymbolAddress((void**)&xz,  g_xz);
    cudaGetSymbolAddress((void**)&hs1, g_hs1);
    cudaGetSymbolAddress((void**)&hb0, g_hb0);
    cudaGetSymbolAddress((void**)&hb1, g_hb1);
    cudaGetSymbolAddress((void**)&d1,  g_d1);
    cudaGetSymbolAddress((void**)&d2,  g_d2);

    cudaFuncSetAttribute(lstm_rec, cudaFuncAttributeMaxDynamicSharedMemorySize, REC_SMEM);

    dim3 ggrid(16, 200);   // N tiles x M tiles

    // layer 1: xz1 = embed[X] @ k1[:E] + b1 ; then recurrence (stores hs1)
    sgemm_xz<1><<<ggrid, 256>>>(X, embed, k1, b1, xz);
    lstm_rec<<<NREC_BLOCKS, 256, REC_SMEM>>>(xz, k1 + (size_t)EE * G4H,
                                             hs1, 1, hb0, hb1, NREC_BLOCKS);

    // layer 2: xz2 = hs1 @ k2[:H] + b2 ; recurrence (final h only)
    sgemm_xz<0><<<ggrid, 256>>>(nullptr, hs1, k2, b2, xz);
    lstm_rec<<<NREC_BLOCKS, 256, REC_SMEM>>>(xz, k2 + (size_t)HH * G4H,
                                             nullptr, 0, hb0, hb1, NREC_BLOCKS);

    // head: T=400 is even, so final h lives in hb0 (written at t=399)
    dense_kernel<<<(BB*DD1 + 255)/256, 256>>>(hb0, w1, bw1, d1, HH,  DD1, 1, 1);
    dense_kernel<<<(BB*DD2 + 255)/256, 256>>>(d1,  w2, bw2, d2, DD1, DD2, 0, 1);
    dense_kernel<<<1, BB*CC>>>(d2, wp, bp, out, DD2, CC, 0, 0);
}

// round 6
// speedup vs baseline: 1.2310x; 1.2310x over previous
#include <cuda_runtime.h>
#include <cuda_bf16.h>
#include <math.h>

// Problem constants
#define VV   32000
#define EE   500
#define HH   500
#define DD1  800
#define DD2  100
#define CC   2
#define BB   64
#define TT   400
#define G4H  2000            // 4*H
#define MM   (BB*TT)         // 25600 rows of the big GEMMs
#define NREC_BLOCKS 125      // 125 * 4 units = 500
#define GSZ  16384           // floats per group slice (256 pairs x 64) = 64KB

// ---------------- scratch (device globals; no allocation allowed) ----------------
__device__ float g_xz [(size_t)MM * G4H];     // 204.8 MB, reused for layer1 and layer2
__device__ float g_hs1[(size_t)MM * HH];      // 51.2 MB
__device__ float g_hb0[2 * GSZ];              // [group][slice]
__device__ float g_hb1[2 * GSZ];
__device__ float g_d1 [BB * DD1];
__device__ float g_d2 [BB * DD2];
// barrier state: counter and sense on separate 128B lines, per group
__device__ unsigned g_gcnt[2][32];
__device__ unsigned g_gsns[2][32];
__device__ unsigned g_icnt[32];
__device__ unsigned g_isns[32];

// ---------------- packed f32x2 helpers ----------------
__device__ __forceinline__ unsigned long long dup2(float v){
    unsigned long long r;
    asm("mov.b64 %0, {%1, %1};" : "=l"(r) : "f"(v));
    return r;
}
__device__ __forceinline__ void fma2(unsigned long long &d,
                                     unsigned long long a,
                                     unsigned long long b){
    asm("fma.rn.f32x2 %0, %1, %2, %3;" : "=l"(d) : "l"(a), "l"(b), "l"(d));
}
__device__ __forceinline__ void unpk2(unsigned long long v, float &lo, float &hi){
    asm("mov.b64 {%0, %1}, %2;" : "=f"(lo), "=f"(hi) : "l"(v));
}

// ---------------- cp.async helpers ----------------
__device__ __forceinline__ void cp_async16(unsigned saddr, const void* gptr){
    asm volatile("cp.async.cg.shared.global [%0], [%1], 16;"
                 :: "r"(saddr), "l"(gptr) : "memory");
}
#define CP_COMMIT()  asm volatile("cp.async.commit_group;" ::: "memory")
#define CP_WAIT0()   asm volatile("cp.async.wait_group 0;" ::: "memory")

// =====================================================================
// SGEMM: C[M=25600, N=2000] = A[M,500] @ Bw[500,2000] + bias
// GATHER=1: A row m -> embed[X[b*T+t]] with m = t*64+b
// =====================================================================
template<int GATHER>
__global__ __launch_bounds__(256)
void sgemm_xz(const int* __restrict__ X, const float* __restrict__ A,
              const float* __restrict__ Bw, const float* __restrict__ bias,
              float* __restrict__ Cmat)
{
    __shared__ float As[8][128];
    __shared__ float Bs[8][128];

    const int tid = threadIdx.x;
    const int tx  = tid & 15;
    const int ty  = tid >> 4;
    const int m0  = blockIdx.y * 128;
    const int n0  = blockIdx.x * 128;

    const int ar  = tid >> 1;
    const int akq = (tid & 1) * 4;
    const float* arow_ptr;
    {
        int m = m0 + ar;
        if (GATHER){
            int t = m >> 6, b = m & 63;
            int tok = X[b * TT + t];
            arow_ptr = A + (size_t)tok * EE;
        } else {
            arow_ptr = A + (size_t)m * HH;
        }
    }
    const int bk = tid >> 5;
    const int bn = (tid & 31) * 4;

    unsigned long long acc[8][4];
    #pragma unroll
    for (int i = 0; i < 8; i++)
        #pragma unroll
        for (int j = 0; j < 4; j++) acc[i][j] = 0ULL;

    const float4 f40 = make_float4(0.f, 0.f, 0.f, 0.f);
    float4 aReg, bReg;
    {
        int k  = akq;
        aReg = (k < 500) ? *(const float4*)(arow_ptr + k) : f40;
        int kb = bk, n = n0 + bn;
        bReg = (kb < 500 && n < G4H) ? *(const float4*)(Bw + (size_t)kb * G4H + n) : f40;
    }

    const int KT = 63;
    for (int kt = 0; kt < KT; kt++){
        __syncthreads();
        As[akq+0][ar] = aReg.x; As[akq+1][ar] = aReg.y;
        As[akq+2][ar] = aReg.z; As[akq+3][ar] = aReg.w;
        *(float4*)(&Bs[bk][bn]) = bReg;
        __syncthreads();

        if (kt + 1 < KT){
            int k = (kt+1)*8 + akq;
            aReg = (k < 500) ? *(const float4*)(arow_ptr + k) : f40;
            int kb = (kt+1)*8 + bk, n = n0 + bn;
            bReg = (kb < 500 && n < G4H) ? *(const float4*)(Bw + (size_t)kb * G4H + n) : f40;
        }

        #pragma unroll
        for (int kk = 0; kk < 8; kk++){
            float4 a0 = *(const float4*)(&As[kk][ty*8]);
            float4 a1 = *(const float4*)(&As[kk][ty*8 + 4]);
            const unsigned long long* bp2 = (const unsigned long long*)(&Bs[kk][tx*8]);
            unsigned long long b0 = bp2[0], b1 = bp2[1], b2 = bp2[2], b3 = bp2[3];
            float av[8] = {a0.x,a0.y,a0.z,a0.w,a1.x,a1.y,a1.z,a1.w};
            #pragma unroll
            for (int i = 0; i < 8; i++){
                unsigned long long ad = dup2(av[i]);
                fma2(acc[i][0], ad, b0);
                fma2(acc[i][1], ad, b1);
                fma2(acc[i][2], ad, b2);
                fma2(acc[i][3], ad, b3);
            }
        }
    }

    const int nc = n0 + tx * 8;
    if (nc < G4H){
        float4 bb0 = *(const float4*)(bias + nc);
        float4 bb1 = *(const float4*)(bias + nc + 4);
        #pragma unroll
        for (int i = 0; i < 8; i++){
            int m = m0 + ty*8 + i;
            float o[8];
            unpk2(acc[i][0], o[0], o[1]);
            unpk2(acc[i][1], o[2], o[3]);
            unpk2(acc[i][2], o[4], o[5]);
            unpk2(acc[i][3], o[6], o[7]);
            float4 r0 = make_float4(o[0]+bb0.x, o[1]+bb0.y, o[2]+bb0.z, o[3]+bb0.w);
            float4 r1 = make_float4(o[4]+bb1.x, o[5]+bb1.y, o[6]+bb1.z, o[7]+bb1.w);
            float* cp = Cmat + (size_t)m * G4H + nc;
            *(float4*)(cp)     = r0;
            *(float4*)(cp + 4) = r1;
        }
    }
}

// =====================================================================
// Per-group grid barrier. bar.sync (CTA-scope acq_rel) orders this group's
// prior stores before lt0's gpu-scope release arrive; pollers acquire-load.
// Counter and sense live on separate 128B lines.
// =====================================================================
__device__ __forceinline__ void group_barrier(int g, int lt, unsigned &sense)
{
    asm volatile("bar.sync %0, 128;" :: "r"(3 + g) : "memory");
    if (lt == 0){
        unsigned target = sense + 1u;
        unsigned old;
        asm volatile("atom.acq_rel.gpu.global.add.u32 %0, [%1], %2;"
                     : "=r"(old) : "l"(&g_gcnt[g][0]), "r"(1u) : "memory");
        if (old == (unsigned)(NREC_BLOCKS - 1)){
            asm volatile("st.relaxed.gpu.global.u32 [%0], %1;"
                         :: "l"(&g_gcnt[g][0]), "r"(0u) : "memory");
            asm volatile("st.release.gpu.global.u32 [%0], %1;"
                         :: "l"(&g_gsns[g][0]), "r"(target) : "memory");
        } else {
            unsigned v;
            do {
                asm volatile("ld.acquire.gpu.global.u32 %0, [%1];"
                             : "=r"(v) : "l"(&g_gsns[g][0]) : "memory");
            } while ((int)(v - target) < 0);
        }
        sense = target;
    }
    asm volatile("bar.sync %0, 128;" :: "r"(3 + g) : "memory");
}

// =====================================================================
// Persistent LSTM recurrence, two independent batch-groups per SM.
// 125 blocks x 256 threads, 1 block/SM. Group g = threads [g*128, g*128+128):
// 32 batches x 4 units, warps of group g land on all 4 SMSPs interleaved with
// the other group's warps -> latency of one group hides under compute of the
// other. Each group has its own grid barrier, h slice (64KB), staging buffer.
// h slice layout: h[g][(k>>1)*64 + (b&31)*2 + (k&1)], pairs padded to 256.
// =====================================================================
__global__ void lstm_rec(const float* __restrict__ xz, const float* __restrict__ Wh,
                         float* __restrict__ hs_out, int store_hs,
                         float* __restrict__ hb0, float* __restrict__ hb1)
{
    extern __shared__ float smem[];
    float* hsm = smem;                 // 2 * 16384 floats (128 KB)
    float* wsm = smem + 2 * GSZ;       // 8000 floats (32 KB)

    const int tid = threadIdx.x;
    const int g   = tid >> 7;          // batch group 0/1
    const int lt  = tid & 127;         // lane within group
    const int bl  = lt & 31;           // batch within group
    const int u   = (lt >> 5) & 3;     // unit within block slice
    const int u0  = blockIdx.x * 4;
    const int uu  = u0 + u;
    const int b   = g * 32 + bl;       // global batch

    unsigned gsense = 0, isense = 0;
    if (lt == 0)
        asm volatile("ld.relaxed.gpu.global.u32 %0, [%1];" : "=r"(gsense) : "l"(&g_gsns[g][0]) : "memory");
    if (tid == 0)
        asm volatile("ld.relaxed.gpu.global.u32 %0, [%1];" : "=r"(isense) : "l"(&g_isns[0]) : "memory");

    // cache weight slice: wsm[k*16 + uw*4 + gate] = Wh[k*2000 + gate*500 + u0+uw]
    for (int idx = tid; idx < 500 * 16; idx += 256){
        int k = idx >> 4, r = idx & 15;
        int uw = r >> 2, gg = r & 3;
        wsm[idx] = Wh[(size_t)k * G4H + gg * HH + u0 + uw];
    }
    // zero both h buffers (incl. pad pairs)
    {
        int gt = blockIdx.x * 256 + tid;
        float4 z4 = make_float4(0.f, 0.f, 0.f, 0.f);
        for (int i = gt; i < (2 * GSZ) / 4; i += NREC_BLOCKS * 256){
            ((float4*)hb0)[i] = z4;
            ((float4*)hb1)[i] = z4;
        }
    }
    // init: full-grid barrier (both groups) so weights/zeros are visible everywhere
    __syncthreads();
    if (tid == 0){
        unsigned target = isense + 1u, old;
        asm volatile("atom.acq_rel.gpu.global.add.u32 %0, [%1], %2;"
                     : "=r"(old) : "l"(&g_icnt[0]), "r"(1u) : "memory");
        if (old == (unsigned)(NREC_BLOCKS - 1)){
            asm volatile("st.relaxed.gpu.global.u32 [%0], %1;" :: "l"(&g_icnt[0]), "r"(0u) : "memory");
            asm volatile("st.release.gpu.global.u32 [%0], %1;" :: "l"(&g_isns[0]), "r"(target) : "memory");
        } else {
            unsigned v;
            do {
                asm volatile("ld.acquire.gpu.global.u32 %0, [%1];" : "=r"(v) : "l"(&g_isns[0]) : "memory");
            } while ((int)(v - target) < 0);
        }
    }
    __syncthreads();

    float* hsg = hsm + g * GSZ;
    const unsigned hsg_s = (unsigned)__cvta_generic_to_shared(hsg);
    float cst = 0.f;
    const int hoff = g * GSZ + (uu >> 1) * 64 + bl * 2 + (uu & 1);
    const float* xzb = xz + (size_t)b * G4H + uu;

    for (int t = 0; t < TT; t++){
        const float* hprev = ((t & 1) ? hb1 : hb0) + g * GSZ;
        float*       hnext = ((t & 1) ? hb0 : hb1);

        // stage this group's 64KB slice (L1-bypass, async)
        #pragma unroll
        for (int i = 0; i < 32; i++){
            int idx = lt + i * 128;
            cp_async16(hsg_s + idx * 16, (const float4*)hprev + idx);
        }
        CP_COMMIT();

        // xz loads fly during staging + compute; added at the END (off chain)
        size_t mrow = (size_t)t * BB * G4H;
        float xi = __ldcs(xzb + mrow);
        float xj = __ldcs(xzb + mrow + 500);
        float xf = __ldcs(xzb + mrow + 1000);
        float xo = __ldcs(xzb + mrow + 1500);

        CP_WAIT0();
        asm volatile("bar.sync %0, 128;" :: "r"(3 + g) : "memory");

        unsigned long long aij = 0ULL, afo = 0ULL;
        #pragma unroll 5
        for (int p = 0; p < 250; p++){
            float2 h2 = *(const float2*)(hsg + p * 64 + bl * 2);
            ulonglong2 wa = *(const ulonglong2*)(wsm + ((2*p    ) * 4 + u) * 4);
            ulonglong2 wb = *(const ulonglong2*)(wsm + ((2*p + 1) * 4 + u) * 4);
            unsigned long long h0 = dup2(h2.x), h1 = dup2(h2.y);
            fma2(aij, h0, wa.x); fma2(afo, h0, wa.y);
            fma2(aij, h1, wb.x); fma2(afo, h1, wb.y);
        }

        float si, sj, sf, so;
        unpk2(aij, si, sj);
        unpk2(afo, sf, so);
        float zi = si + xi, zj = sj + xj, zf = sf + xf, zo = so + xo;

        float ig = 1.f / (1.f + expf(-zi));
        float fg = 1.f / (1.f + expf(-(zf + 1.f)));
        float og = 1.f / (1.f + expf(-zo));
        float jt = tanhf(zj);
        cst = fg * cst + ig * jt;
        float hv = og * tanhf(cst);

        __stcg(hnext + hoff, hv);
        if (store_hs)
            hs_out[(size_t)(t * BB + b) * HH + uu] = hv;

        group_barrier(g, lt, gsense);
    }
}

// =====================================================================
// Small dense layers. transposed_in: in uses the grouped pair-packed h layout.
// =====================================================================
__global__ void dense_kernel(const float* __restrict__ in, const float* __restrict__ W,
                             const float* __restrict__ bias, float* __restrict__ out,
                             int Kdim, int Ndim, int transposed_in, int do_relu)
{
    int gidx = blockIdx.x * blockDim.x + threadIdx.x;
    if (gidx >= BB * Ndim) return;
    int bv = gidx / Ndim;
    int j  = gidx - bv * Ndim;
    float acc = bias[j];
    if (transposed_in){
        int base = (bv >> 5) * GSZ + (bv & 31) * 2;
        for (int k = 0; k < Kdim; k++)
            acc += in[base + (k >> 1) * 64 + (k & 1)] * W[k * Ndim + j];
    } else {
        for (int k = 0; k < Kdim; k++)
            acc += in[bv * Kdim + k] * W[k * Ndim + j];
    }
    out[gidx] = do_relu ? fmaxf(acc, 0.f) : acc;
}

// =====================================================================
// Launch
// =====================================================================
#define REC_SMEM ((2*GSZ + 500*16) * (int)sizeof(float))   // 163072 B

extern "C" void kernel_launch(void* const* d_in, const int* in_sizes, int n_in,
                              void* d_out, int out_size)
{
    const int*   X     = (const int*)  d_in[0];
    const float* embed = (const float*)d_in[1];
    const float* k1    = (const float*)d_in[2];
    const float* b1    = (const float*)d_in[3];
    const float* k2    = (const float*)d_in[4];
    const float* b2    = (const float*)d_in[5];
    const float* w1    = (const float*)d_in[6];
    const float* bw1   = (const float*)d_in[7];
    const float* w2    = (const float*)d_in[8];
    const float* bw2   = (const float*)d_in[9];
    const float* wp    = (const float*)d_in[10];
    const float* bp    = (const float*)d_in[11];
    float* out = (float*)d_out;

    float *xz, *hs1, *hb0, *hb1, *d1, *d2;
    cudaGetSymbolAddress((void**)&xz,  g_xz);
    cudaGetSymbolAddress((void**)&hs1, g_hs1);
    cudaGetSymbolAddress((void**)&hb0, g_hb0);
    cudaGetSymbolAddress((void**)&hb1, g_hb1);
    cudaGetSymbolAddress((void**)&d1,  g_d1);
    cudaGetSymbolAddress((void**)&d2,  g_d2);

    cudaFuncSetAttribute(lstm_rec, cudaFuncAttributeMaxDynamicSharedMemorySize, REC_SMEM);

    dim3 ggrid(16, 200);   // N tiles x M tiles

    // layer 1: xz1 = embed[X] @ k1[:E] + b1 ; then recurrence (stores hs1)
    sgemm_xz<1><<<ggrid, 256>>>(X, embed, k1, b1, xz);
    lstm_rec<<<NREC_BLOCKS, 256, REC_SMEM>>>(xz, k1 + (size_t)EE * G4H,
                                             hs1, 1, hb0, hb1);

    // layer 2: xz2 = hs1 @ k2[:H] + b2 ; recurrence (final h only)
    sgemm_xz<0><<<ggrid, 256>>>(nullptr, hs1, k2, b2, xz);
    lstm_rec<<<NREC_BLOCKS, 256, REC_SMEM>>>(xz, k2 + (size_t)HH * G4H,
                                             nullptr, 0, hb0, hb1);

    // head: T=400 even -> final h in hb0 (written at t=399)
    dense_kernel<<<(BB*DD1 + 255)/256, 256>>>(hb0, w1, bw1, d1, HH,  DD1, 1, 1);
    dense_kernel<<<(BB*DD2 + 255)/256, 256>>>(d1,  w2, bw2, d2, DD1, DD2, 0, 1);
    dense_kernel<<<1, BB*CC>>>(d2, wp, bp, out, DD2, CC, 0, 0);
}